// round 1
// baseline (speedup 1.0000x reference)
#include <cuda_runtime.h>
#include <math.h>

// Problem constants (fixed by the dataset)
#define EMB     512
#define HIDDEN  1024
#define HALF_H  512
#define BATCH   256
#define SEQLEN  512
#define NTOK    (BATCH * SEQLEN)   // 131072

// 256 MB scratch for hid1 = relu(seq@w1x+b1x)  (device global: allocation-free)
__device__ float g_hid[(size_t)NTOK * HALF_H];

// ---------------------------------------------------------------------------
// Classic register-blocked SGEMM: C[M,N] = act(A[M,K] @ W[K,N] + bias)
// BM=BN=128, BK=8, 256 threads, 8x8 outputs/thread (split 4+4 micro-tiles).
// M,N divisible by 128; K divisible by 8 (holds for all our shapes).
// ---------------------------------------------------------------------------
template <bool RELU>
__global__ __launch_bounds__(256, 2)
void sgemm_bias_kernel(const float* __restrict__ A,
                       const float* __restrict__ W,
                       const float* __restrict__ bias,
                       float* __restrict__ C,
                       int M, int N, int K)
{
    __shared__ float As[8][128];   // transposed A tile
    __shared__ float Bs[8][128];

    const int tid = threadIdx.x;
    const int m0  = blockIdx.y * 128;
    const int n0  = blockIdx.x * 128;

    const int tr = tid >> 4;       // 0..15 (row group)
    const int tc = tid & 15;       // 0..15 (col group)

    // loader mapping
    const int a_row = tid >> 1;          // 0..127
    const int a_col = (tid & 1) * 4;     // 0 or 4
    const int b_row = tid >> 5;          // 0..7
    const int b_col = (tid & 31) * 4;    // 0..124

    const float* Aptr = A + (size_t)(m0 + a_row) * K + a_col;
    const float* Wptr = W + (size_t)b_row * N + n0 + b_col;

    float acc[8][8];
#pragma unroll
    for (int i = 0; i < 8; i++)
#pragma unroll
        for (int j = 0; j < 8; j++) acc[i][j] = 0.0f;

    for (int k0 = 0; k0 < K; k0 += 8) {
        // prefetch into registers before the barrier
        const float4 av = *(const float4*)(Aptr + k0);
        const float4 bv = *(const float4*)(Wptr + (size_t)k0 * N);

        __syncthreads();   // previous tile fully consumed
        As[a_col + 0][a_row] = av.x;
        As[a_col + 1][a_row] = av.y;
        As[a_col + 2][a_row] = av.z;
        As[a_col + 3][a_row] = av.w;
        *(float4*)&Bs[b_row][b_col] = bv;
        __syncthreads();

#pragma unroll
        for (int kk = 0; kk < 8; kk++) {
            float ra[8], rb[8];
            *(float4*)&ra[0] = *(const float4*)&As[kk][tr * 4];
            *(float4*)&ra[4] = *(const float4*)&As[kk][64 + tr * 4];
            *(float4*)&rb[0] = *(const float4*)&Bs[kk][tc * 4];
            *(float4*)&rb[4] = *(const float4*)&Bs[kk][64 + tc * 4];
#pragma unroll
            for (int i = 0; i < 8; i++)
#pragma unroll
                for (int j = 0; j < 8; j++)
                    acc[i][j] = fmaf(ra[i], rb[j], acc[i][j]);
        }
    }

    // epilogue: bias (+relu), two float4 column groups per output row
    const int c0 = n0 + tc * 4;
    const int c1 = n0 + 64 + tc * 4;
    float4 bias0 = *(const float4*)&bias[c0];
    float4 bias1 = *(const float4*)&bias[c1];

#pragma unroll
    for (int i = 0; i < 8; i++) {
        const int row = m0 + ((i < 4) ? (tr * 4 + i) : (64 + tr * 4 + (i - 4)));
        float4 v0, v1;
        v0.x = acc[i][0] + bias0.x;  v0.y = acc[i][1] + bias0.y;
        v0.z = acc[i][2] + bias0.z;  v0.w = acc[i][3] + bias0.w;
        v1.x = acc[i][4] + bias1.x;  v1.y = acc[i][5] + bias1.y;
        v1.z = acc[i][6] + bias1.z;  v1.w = acc[i][7] + bias1.w;
        if (RELU) {
            v0.x = fmaxf(v0.x, 0.f); v0.y = fmaxf(v0.y, 0.f);
            v0.z = fmaxf(v0.z, 0.f); v0.w = fmaxf(v0.w, 0.f);
            v1.x = fmaxf(v1.x, 0.f); v1.y = fmaxf(v1.y, 0.f);
            v1.z = fmaxf(v1.z, 0.f); v1.w = fmaxf(v1.w, 0.f);
        }
        *(float4*)&C[(size_t)row * N + c0] = v0;
        *(float4*)&C[(size_t)row * N + c1] = v1;
    }
}

// ---------------------------------------------------------------------------
// Recurrence: one CTA owns 2 batch rows, loops over all 512 time steps.
// h lives in SMEM; weights streamed from L2 (this is the known L2 bottleneck,
// to be fixed in a later round). No inter-CTA sync needed (batches independent).
// out[] holds xh on entry per (b,t) and is overwritten with h_t.
// ---------------------------------------------------------------------------
__global__ __launch_bounds__(512, 1)
void recurrence_kernel(const float* __restrict__ W1h,  // [1024, 512]
                       const float* __restrict__ b1h,  // [512]
                       const float* __restrict__ W2h,  // [512, 1024]
                       const float* __restrict__ b2h,  // [1024]
                       const int*   __restrict__ lens, // [256]
                       float* __restrict__ out)        // [256, 512, 1024]
{
    __shared__ float hs[2][HIDDEN];   // current h for 2 batches
    __shared__ float h1s[2][HALF_H];  // relu(h@W1h+b1h)

    const int tid = threadIdx.x;      // 0..511
    const int b0  = blockIdx.x * 2;

    for (int i = tid; i < 2 * HIDDEN; i += 512)
        ((float*)hs)[i] = 0.0f;

    const int len0 = lens[b0];
    const int len1 = lens[b0 + 1];

    const float bb1  = b1h[tid];
    const float bb2a = b2h[tid];
    const float bb2b = b2h[tid + HALF_H];

    __syncthreads();

    for (int t = 0; t < SEQLEN; t++) {
        // ---- phase A: h1[:, tid] = relu(b1h + h @ W1h[:, tid]) ----
        float a0 = bb1, a1 = bb1;
        const float* wp = W1h + tid;
#pragma unroll 8
        for (int k = 0; k < HIDDEN; k++) {
            const float w = wp[(size_t)k * HALF_H];
            a0 = fmaf(hs[0][k], w, a0);
            a1 = fmaf(hs[1][k], w, a1);
        }
        h1s[0][tid] = fmaxf(a0, 0.0f);
        h1s[1][tid] = fmaxf(a1, 0.0f);
        __syncthreads();

        // ---- phase B: cols tid and tid+512 of h2 = h1 @ W2h + b2h ----
        float c00 = bb2a, c01 = bb2b, c10 = bb2a, c11 = bb2b;
        const float* wq = W2h + tid;
#pragma unroll 8
        for (int k = 0; k < HALF_H; k++) {
            const float w0 = wq[(size_t)k * HIDDEN];
            const float w1 = wq[(size_t)k * HIDDEN + HALF_H];
            const float p0 = h1s[0][k];
            const float p1 = h1s[1][k];
            c00 = fmaf(p0, w0, c00);
            c01 = fmaf(p0, w1, c01);
            c10 = fmaf(p1, w0, c10);
            c11 = fmaf(p1, w1, c11);
        }

        // ---- update h, write output (out currently holds xh at (b,t)) ----
        const size_t o0 = ((size_t)b0 * SEQLEN + t) * HIDDEN;
        const size_t o1 = ((size_t)(b0 + 1) * SEQLEN + t) * HIDDEN;

        const float n00 = tanhf(out[o0 + tid]          + c00);
        const float n01 = tanhf(out[o0 + tid + HALF_H] + c01);
        const float n10 = tanhf(out[o1 + tid]          + c10);
        const float n11 = tanhf(out[o1 + tid + HALF_H] + c11);

        const bool m0 = (t < len0);
        const bool m1 = (t < len1);

        const float h00 = m0 ? n00 : hs[0][tid];
        const float h01 = m0 ? n01 : hs[0][tid + HALF_H];
        const float h10 = m1 ? n10 : hs[1][tid];
        const float h11 = m1 ? n11 : hs[1][tid + HALF_H];

        hs[0][tid]          = h00;
        hs[0][tid + HALF_H] = h01;
        hs[1][tid]          = h10;
        hs[1][tid + HALF_H] = h11;

        out[o0 + tid]          = h00;
        out[o0 + tid + HALF_H] = h01;
        out[o1 + tid]          = h10;
        out[o1 + tid + HALF_H] = h11;

        __syncthreads();   // hs fully updated before next phase A
    }
}

// ---------------------------------------------------------------------------
extern "C" void kernel_launch(void* const* d_in, const int* in_sizes, int n_in,
                              void* d_out, int out_size)
{
    const float* seq  = (const float*)d_in[0];
    const int*   lens = (const int*)  d_in[1];
    const float* w1x  = (const float*)d_in[2];
    const float* b1x  = (const float*)d_in[3];
    const float* w2x  = (const float*)d_in[4];
    const float* b2x  = (const float*)d_in[5];
    const float* w1h  = (const float*)d_in[6];
    const float* b1h  = (const float*)d_in[7];
    const float* w2h  = (const float*)d_in[8];
    const float* b2h  = (const float*)d_in[9];
    float* out = (float*)d_out;

    float* hid = nullptr;
    cudaGetSymbolAddress((void**)&hid, g_hid);

    // K1: hid = relu(seq @ w1x + b1x)   [131072,512] = [131072,512]@[512,512]
    sgemm_bias_kernel<true><<<dim3(HALF_H / 128, NTOK / 128), 256>>>(
        seq, w1x, b1x, hid, NTOK, HALF_H, EMB);

    // K2: out = hid @ w2x + b2x         [131072,1024] = [131072,512]@[512,1024]
    sgemm_bias_kernel<false><<<dim3(HIDDEN / 128, NTOK / 128), 256>>>(
        hid, w2x, b2x, out, NTOK, HIDDEN, HALF_H);

    // K3: 512-step recurrence, 2 batch rows per CTA, xh read from / h written to out
    recurrence_kernel<<<BATCH / 2, 512>>>(w1h, b1h, w2h, b2h, lens, out);
}

// round 2
// speedup vs baseline: 2.6731x; 2.6731x over previous
#include <cuda_runtime.h>
#include <cuda_bf16.h>
#include <math.h>
#include <string.h>

// Problem constants (fixed by the dataset)
#define EMB     512
#define HIDDEN  1024
#define HALF_H  512
#define BATCH   256
#define SEQLEN  512
#define NTOK    (BATCH * SEQLEN)   // 131072

#define NCTA    128
#define NTHR    256

// ---------------------------------------------------------------------------
// Device globals (allocation-free scratch)
// ---------------------------------------------------------------------------
__device__ float    g_hid[(size_t)NTOK * HALF_H];            // phase-1 intermediate
__device__ unsigned short g_h_bf16[BATCH * HIDDEN];          // h (bf16) for MMA input
__device__ unsigned short g_h1_bf16[BATCH * HALF_H];         // relu(h@W1h+b1h) (bf16)
__device__ volatile unsigned g_bar_gen;                      // grid barrier generation
__device__ unsigned g_bar_cnt;                               // grid barrier counter

// ---------------------------------------------------------------------------
// Helpers
// ---------------------------------------------------------------------------
static __device__ __forceinline__ unsigned smem_u32(const void* p) {
    unsigned a;
    asm("{ .reg .u64 t; cvta.to.shared.u64 t, %1; cvt.u32.u64 %0, t; }"
        : "=r"(a) : "l"(p));
    return a;
}

static __device__ __forceinline__ void ldsm_x4(unsigned& r0, unsigned& r1,
                                               unsigned& r2, unsigned& r3,
                                               unsigned addr) {
    asm volatile("ldmatrix.sync.aligned.m8n8.x4.shared.b16 {%0,%1,%2,%3}, [%4];"
                 : "=r"(r0), "=r"(r1), "=r"(r2), "=r"(r3) : "r"(addr));
}

static __device__ __forceinline__ void ldsm_x2(unsigned& r0, unsigned& r1,
                                               unsigned addr) {
    asm volatile("ldmatrix.sync.aligned.m8n8.x2.shared.b16 {%0,%1}, [%2];"
                 : "=r"(r0), "=r"(r1) : "r"(addr));
}

static __device__ __forceinline__ void mma_bf16(float& c0, float& c1, float& c2, float& c3,
                                                unsigned a0, unsigned a1, unsigned a2, unsigned a3,
                                                unsigned b0, unsigned b1) {
    asm volatile("mma.sync.aligned.m16n8k16.row.col.f32.bf16.bf16.f32 "
                 "{%0,%1,%2,%3}, {%4,%5,%6,%7}, {%8,%9}, {%0,%1,%2,%3};"
                 : "+f"(c0), "+f"(c1), "+f"(c2), "+f"(c3)
                 : "r"(a0), "r"(a1), "r"(a2), "r"(a3), "r"(b0), "r"(b1));
}

static __device__ __forceinline__ unsigned pack_bf16(float x, float y) {
    __nv_bfloat162 v = __floats2bfloat162_rn(x, y);
    unsigned u;
    memcpy(&u, &v, 4);
    return u;
}

static __device__ __forceinline__ unsigned short f2bf(float x) {
    __nv_bfloat16 v = __float2bfloat16(x);
    unsigned short u;
    memcpy(&u, &v, 2);
    return u;
}

// Grid barrier: all NCTA CTAs resident (grid <= SM count), spin on generation.
static __device__ __forceinline__ void gridbar() {
    __threadfence();                 // release: each thread flushes its stores
    __syncthreads();
    if (threadIdx.x == 0) {
        unsigned gen = g_bar_gen;
        if (atomicAdd(&g_bar_cnt, 1) == NCTA - 1) {
            g_bar_cnt = 0;
            __threadfence();
            g_bar_gen = gen + 1;
        } else {
            while (g_bar_gen == gen) { }
            __threadfence();         // acquire
        }
    }
    __syncthreads();
}

// ---------------------------------------------------------------------------
// Classic register-blocked SGEMM: C[M,N] = act(A[M,K] @ W[K,N] + bias)
// (unchanged from round 1 — fp32-FMA bound, to be replaced in a later round)
// ---------------------------------------------------------------------------
template <bool RELU>
__global__ __launch_bounds__(256, 2)
void sgemm_bias_kernel(const float* __restrict__ A,
                       const float* __restrict__ W,
                       const float* __restrict__ bias,
                       float* __restrict__ C,
                       int M, int N, int K)
{
    __shared__ float As[8][128];
    __shared__ float Bs[8][128];

    const int tid = threadIdx.x;
    const int m0  = blockIdx.y * 128;
    const int n0  = blockIdx.x * 128;

    const int tr = tid >> 4;
    const int tc = tid & 15;

    const int a_row = tid >> 1;
    const int a_col = (tid & 1) * 4;
    const int b_row = tid >> 5;
    const int b_col = (tid & 31) * 4;

    const float* Aptr = A + (size_t)(m0 + a_row) * K + a_col;
    const float* Wptr = W + (size_t)b_row * N + n0 + b_col;

    float acc[8][8];
#pragma unroll
    for (int i = 0; i < 8; i++)
#pragma unroll
        for (int j = 0; j < 8; j++) acc[i][j] = 0.0f;

    for (int k0 = 0; k0 < K; k0 += 8) {
        const float4 av = *(const float4*)(Aptr + k0);
        const float4 bv = *(const float4*)(Wptr + (size_t)k0 * N);

        __syncthreads();
        As[a_col + 0][a_row] = av.x;
        As[a_col + 1][a_row] = av.y;
        As[a_col + 2][a_row] = av.z;
        As[a_col + 3][a_row] = av.w;
        *(float4*)&Bs[b_row][b_col] = bv;
        __syncthreads();

#pragma unroll
        for (int kk = 0; kk < 8; kk++) {
            float ra[8], rb[8];
            *(float4*)&ra[0] = *(const float4*)&As[kk][tr * 4];
            *(float4*)&ra[4] = *(const float4*)&As[kk][64 + tr * 4];
            *(float4*)&rb[0] = *(const float4*)&Bs[kk][tc * 4];
            *(float4*)&rb[4] = *(const float4*)&Bs[kk][64 + tc * 4];
#pragma unroll
            for (int i = 0; i < 8; i++)
#pragma unroll
                for (int j = 0; j < 8; j++)
                    acc[i][j] = fmaf(ra[i], rb[j], acc[i][j]);
        }
    }

    const int c0 = n0 + tc * 4;
    const int c1 = n0 + 64 + tc * 4;
    float4 bias0 = *(const float4*)&bias[c0];
    float4 bias1 = *(const float4*)&bias[c1];

#pragma unroll
    for (int i = 0; i < 8; i++) {
        const int row = m0 + ((i < 4) ? (tr * 4 + i) : (64 + tr * 4 + (i - 4)));
        float4 v0, v1;
        v0.x = acc[i][0] + bias0.x;  v0.y = acc[i][1] + bias0.y;
        v0.z = acc[i][2] + bias0.z;  v0.w = acc[i][3] + bias0.w;
        v1.x = acc[i][4] + bias1.x;  v1.y = acc[i][5] + bias1.y;
        v1.z = acc[i][6] + bias1.z;  v1.w = acc[i][7] + bias1.w;
        if (RELU) {
            v0.x = fmaxf(v0.x, 0.f); v0.y = fmaxf(v0.y, 0.f);
            v0.z = fmaxf(v0.z, 0.f); v0.w = fmaxf(v0.w, 0.f);
            v1.x = fmaxf(v1.x, 0.f); v1.y = fmaxf(v1.y, 0.f);
            v1.z = fmaxf(v1.z, 0.f); v1.w = fmaxf(v1.w, 0.f);
        }
        *(float4*)&C[(size_t)row * N + c0] = v0;
        *(float4*)&C[(size_t)row * N + c1] = v1;
    }
}

// ---------------------------------------------------------------------------
// Persistent tensor-core recurrence kernel.
// 128 CTAs, 256 threads. Weights SMEM-resident as bf16.
// Per step: Phase A (h@W1h -> h1), grid barrier, Phase B (h1@W2h + xh -> h),
// grid barrier. h exchanged as bf16 via L2 (__ldcg/__stcg).
// ---------------------------------------------------------------------------
// SMEM layout (bytes); strides padded so row stride mod 128B == 16B (ldmatrix
// conflict-free: 8 consecutive rows hit distinct 4-word bank groups).
#define WS1_STRIDE 1032                     // halves per row (1024 + 8)
#define WS2_STRIDE 520                      // halves per row (512 + 8)
#define ACH_STRIDE 264                      // halves per row (256 + 8)
#define H1S_STRIDE 520                      // halves per row (512 + 8)

#define OFF_WS1  0
#define OFF_WS2  (OFF_WS1 + 32 * WS1_STRIDE * 2)        // 66048
#define OFF_ACH  (OFF_WS2 + 64 * WS2_STRIDE * 2)        // 132608
#define OFF_H1S  (OFF_ACH + 32 * ACH_STRIDE * 2)        // 149504
#define OFF_B1   (OFF_H1S + 32 * H1S_STRIDE * 2)        // 182784
#define OFF_B2   (OFF_B1 + 32 * 4)                      // 182912
#define OFF_LEN  (OFF_B2 + 64 * 4)                      // 183168
#define SMEM_TOTAL (OFF_LEN + 32 * 4)                   // 183296

__global__ __launch_bounds__(NTHR, 1)
void recurrence_tc(const float* __restrict__ W1h,  // [1024, 512]
                   const float* __restrict__ b1h,  // [512]
                   const float* __restrict__ W2h,  // [512, 1024]
                   const float* __restrict__ b2h,  // [1024]
                   const int*   __restrict__ lens, // [256]
                   float* __restrict__ out)        // [256, 512, 1024] holds xh
{
    extern __shared__ char smem[];
    unsigned short* ws1 = (unsigned short*)(smem + OFF_WS1);
    unsigned short* ws2 = (unsigned short*)(smem + OFF_WS2);
    unsigned short* ach = (unsigned short*)(smem + OFF_ACH);
    unsigned short* h1s = (unsigned short*)(smem + OFF_H1S);
    float* b1s = (float*)(smem + OFF_B1);
    float* b2s = (float*)(smem + OFF_B2);
    int*   lns = (int*)(smem + OFF_LEN);

    const unsigned u_ws1 = smem_u32(ws1);
    const unsigned u_ws2 = smem_u32(ws2);
    const unsigned u_ach = smem_u32(ach);
    const unsigned u_h1s = smem_u32(h1s);

    const int tid  = threadIdx.x;
    const int cta  = blockIdx.x;
    const int wid  = tid >> 5;
    const int lane = tid & 31;
    const int quad = lane >> 2;     // 0..7
    const int tq   = lane & 3;      // 0..3

    // Tile assignment
    const int rA = (cta >> 4) * 32;          // h rows for phase A   (8 groups)
    const int cA = (cta & 15) * 32;          // h1 cols for phase A  (16 groups)
    const int rB = (cta >> 4) * 32;          // batch rows for phase B
    const int cB = (cta & 15) * 64;          // h cols for phase B

    // Warp sub-tiles
    const int mh = wid & 1;                  // m-half (0/1) -> rows mh*16..+16
    const int nb = wid >> 1;                 // phase A: n-block (0..3) of 8
    const int np = wid >> 1;                 // phase B: n-pair  (0..3) of 16

    // ---- init: convert weight slabs to bf16 in SMEM ----
    for (int i = tid; i < 1024 * 32; i += NTHR) {
        int k = i >> 5, n = i & 31;
        ws1[n * WS1_STRIDE + k] = f2bf(W1h[(size_t)k * HALF_H + cA + n]);
    }
    for (int i = tid; i < 512 * 64; i += NTHR) {
        int k = i >> 6, n = i & 63;
        ws2[n * WS2_STRIDE + k] = f2bf(W2h[(size_t)k * HIDDEN + cB + n]);
    }
    if (tid < 32) { b1s[tid] = b1h[cA + tid]; lns[tid] = lens[rB + tid]; }
    if (tid < 64) b2s[tid] = b2h[cB + tid];

    // zero h (bf16, global): 131072 words / 128 CTAs = 1024 words per CTA
    {
        unsigned* hz = (unsigned*)g_h_bf16;
        for (int i = tid; i < 1024; i += NTHR) hz[cta * 1024 + i] = 0u;
    }

    // h master copy in registers: phase-B output elements owned by this thread.
    // Layout: [blk(2)][j(4)] matching accumulator layout.
    float hreg[2][4];
#pragma unroll
    for (int b = 0; b < 2; b++)
#pragma unroll
        for (int j = 0; j < 4; j++) hreg[b][j] = 0.0f;

    __syncthreads();
    gridbar();

    // ldmatrix address components (constant across steps)
    // Phase A / B "A" fragment: thread i -> matrix j=i/8, row (j&1)*8 + i%8, kq=(j>>1)*8
    const int aj   = lane >> 3;
    const int arow = mh * 16 + (aj & 1) * 8 + (lane & 7);
    const int akq  = (aj >> 1) * 8;
    // "B" fragment (x2): lanes 0..15 meaningful, mirror for 16..31
    const int li   = lane & 15;
    const int brow_in = li & 7;
    const int bkq  = (li >> 3) * 8;

    for (int t = 0; t < SEQLEN; t++) {
        // ================= PHASE A =================
        float ca[4] = {0.f, 0.f, 0.f, 0.f};
        for (int ch = 0; ch < 4; ch++) {
            const int kbase = ch * 256;
            __syncthreads();
            // stage h rows [rA..rA+32), k [kbase..kbase+256) as bf16
#pragma unroll
            for (int j = 0; j < 4; j++) {
                int lin  = tid + j * NTHR;          // 0..1023
                int row  = lin >> 5;                // /32
                int colv = (lin & 31) * 8;
                uint4 v = __ldcg((const uint4*)(g_h_bf16 + (size_t)(rA + row) * HIDDEN + kbase + colv));
                *(uint4*)(ach + row * ACH_STRIDE + colv) = v;
            }
            __syncthreads();
#pragma unroll 4
            for (int kk = 0; kk < 256; kk += 16) {
                unsigned a0, a1, a2, a3, b0, b1;
                ldsm_x4(a0, a1, a2, a3, u_ach + (unsigned)(arow * ACH_STRIDE + kk + akq) * 2);
                ldsm_x2(b0, b1, u_ws1 + (unsigned)((nb * 8 + brow_in) * WS1_STRIDE + kbase + kk + bkq) * 2);
                mma_bf16(ca[0], ca[1], ca[2], ca[3], a0, a1, a2, a3, b0, b1);
            }
        }
        // epilogue: h1 = relu(acc + b1) -> bf16 pairs
        {
            const int n = nb * 8 + tq * 2;
            const int m0w = mh * 16 + quad;
            float v0 = fmaxf(ca[0] + b1s[n], 0.f);
            float v1 = fmaxf(ca[1] + b1s[n + 1], 0.f);
            float v2 = fmaxf(ca[2] + b1s[n], 0.f);
            float v3 = fmaxf(ca[3] + b1s[n + 1], 0.f);
            __stcg((unsigned*)(g_h1_bf16 + (size_t)(rA + m0w) * HALF_H + cA + n), pack_bf16(v0, v1));
            __stcg((unsigned*)(g_h1_bf16 + (size_t)(rA + m0w + 8) * HALF_H + cA + n), pack_bf16(v2, v3));
        }
        gridbar();

        // ================= PHASE B =================
        __syncthreads();
        // stage h1 rows [rB..rB+32), all 512 cols
#pragma unroll
        for (int j = 0; j < 8; j++) {
            int lin  = tid + j * NTHR;              // 0..2047
            int row  = lin >> 6;                    // /64
            int colv = (lin & 63) * 8;
            uint4 v = __ldcg((const uint4*)(g_h1_bf16 + (size_t)(rB + row) * HALF_H + colv));
            *(uint4*)(h1s + row * H1S_STRIDE + colv) = v;
        }
        __syncthreads();

        float cb[2][4];
#pragma unroll
        for (int b = 0; b < 2; b++)
#pragma unroll
            for (int j = 0; j < 4; j++) cb[b][j] = 0.f;

#pragma unroll 4
        for (int kk = 0; kk < 512; kk += 16) {
            unsigned a0, a1, a2, a3;
            ldsm_x4(a0, a1, a2, a3, u_h1s + (unsigned)(arow * H1S_STRIDE + kk + akq) * 2);
#pragma unroll
            for (int b = 0; b < 2; b++) {
                unsigned b0, b1;
                ldsm_x2(b0, b1, u_ws2 + (unsigned)((np * 16 + b * 8 + brow_in) * WS2_STRIDE + kk + bkq) * 2);
                mma_bf16(cb[b][0], cb[b][1], cb[b][2], cb[b][3], a0, a1, a2, a3, b0, b1);
            }
        }

        // epilogue: h_new = tanh(xh + hh + b2), mask, write out + g_h_bf16
#pragma unroll
        for (int b = 0; b < 2; b++) {
            const int n = np * 16 + b * 8 + tq * 2;
            const float bb0 = b2s[n], bb1 = b2s[n + 1];
#pragma unroll
            for (int half = 0; half < 2; half++) {
                const int m = mh * 16 + quad + half * 8;
                const int bat = rB + m;
                const int col = cB + n;
                const size_t oidx = ((size_t)bat * SEQLEN + t) * HIDDEN + col;
                float xh0 = out[oidx], xh1 = out[oidx + 1];
                float nv0 = tanhf(xh0 + cb[b][half * 2 + 0] + bb0);
                float nv1 = tanhf(xh1 + cb[b][half * 2 + 1] + bb1);
                bool ok = t < lns[m];
                float h0 = ok ? nv0 : hreg[b][half * 2 + 0];
                float h1 = ok ? nv1 : hreg[b][half * 2 + 1];
                hreg[b][half * 2 + 0] = h0;
                hreg[b][half * 2 + 1] = h1;
                out[oidx]     = h0;
                out[oidx + 1] = h1;
                __stcg((unsigned*)(g_h_bf16 + (size_t)bat * HIDDEN + col), pack_bf16(h0, h1));
            }
        }
        gridbar();
    }
}

// ---------------------------------------------------------------------------
extern "C" void kernel_launch(void* const* d_in, const int* in_sizes, int n_in,
                              void* d_out, int out_size)
{
    const float* seq  = (const float*)d_in[0];
    const int*   lens = (const int*)  d_in[1];
    const float* w1x  = (const float*)d_in[2];
    const float* b1x  = (const float*)d_in[3];
    const float* w2x  = (const float*)d_in[4];
    const float* b2x  = (const float*)d_in[5];
    const float* w1h  = (const float*)d_in[6];
    const float* b1h  = (const float*)d_in[7];
    const float* w2h  = (const float*)d_in[8];
    const float* b2h  = (const float*)d_in[9];
    float* out = (float*)d_out;

    float* hid = nullptr;
    cudaGetSymbolAddress((void**)&hid, g_hid);

    static bool attr_set = false;
    if (!attr_set) {
        cudaFuncSetAttribute(recurrence_tc,
                             cudaFuncAttributeMaxDynamicSharedMemorySize, SMEM_TOTAL);
        attr_set = true;
    }

    // K1: hid = relu(seq @ w1x + b1x)
    sgemm_bias_kernel<true><<<dim3(HALF_H / 128, NTOK / 128), 256>>>(
        seq, w1x, b1x, hid, NTOK, HALF_H, EMB);

    // K2: out = hid @ w2x + b2x   (xh)
    sgemm_bias_kernel<false><<<dim3(HIDDEN / 128, NTOK / 128), 256>>>(
        hid, w2x, b2x, out, NTOK, HIDDEN, HALF_H);

    // K3: persistent tensor-core recurrence (weights SMEM-resident)
    recurrence_tc<<<NCTA, NTHR, SMEM_TOTAL>>>(w1h, b1h, w2h, b2h, lens, out);
}

// round 3
// speedup vs baseline: 3.0445x; 1.1390x over previous
#include <cuda_runtime.h>
#include <cuda_bf16.h>
#include <math.h>
#include <string.h>

// Problem constants (fixed by the dataset)
#define EMB     512
#define HIDDEN  1024
#define HALF_H  512
#define BATCH   256
#define SEQLEN  512
#define NTOK    (BATCH * SEQLEN)   // 131072
#define KP      1536               // 3 * 512 packed-K for split-bf16 GEMMs

#define NCTA    128
#define NTHR    256

// ---------------------------------------------------------------------------
// Device globals (allocation-free scratch)
// ---------------------------------------------------------------------------
__device__ unsigned short g_a1p[(size_t)NTOK * KP];    // packed seq   [M][1536]
__device__ unsigned short g_hidp[(size_t)NTOK * KP];   // packed hid1  [M][1536]
__device__ unsigned short g_w1xp[HALF_H * KP];         // packed w1x   [512][1536] (n-major)
__device__ unsigned short g_w2xp[HIDDEN * KP];         // packed w2x   [1024][1536] (n-major)
__device__ unsigned short g_h_bf16[BATCH * HIDDEN];    // h (bf16)
__device__ unsigned short g_h1_bf16[BATCH * HALF_H];   // relu(h@W1h+b1h) (bf16)
__device__ volatile unsigned g_bar_gen;
__device__ unsigned g_bar_cnt;

// ---------------------------------------------------------------------------
// Helpers
// ---------------------------------------------------------------------------
static __device__ __forceinline__ unsigned smem_u32(const void* p) {
    unsigned a;
    asm("{ .reg .u64 t; cvta.to.shared.u64 t, %1; cvt.u32.u64 %0, t; }"
        : "=r"(a) : "l"(p));
    return a;
}

static __device__ __forceinline__ void ldsm_x4(unsigned& r0, unsigned& r1,
                                               unsigned& r2, unsigned& r3,
                                               unsigned addr) {
    asm volatile("ldmatrix.sync.aligned.m8n8.x4.shared.b16 {%0,%1,%2,%3}, [%4];"
                 : "=r"(r0), "=r"(r1), "=r"(r2), "=r"(r3) : "r"(addr));
}

static __device__ __forceinline__ void ldsm_x2(unsigned& r0, unsigned& r1,
                                               unsigned addr) {
    asm volatile("ldmatrix.sync.aligned.m8n8.x2.shared.b16 {%0,%1}, [%2];"
                 : "=r"(r0), "=r"(r1) : "r"(addr));
}

static __device__ __forceinline__ void mma_bf16(float& c0, float& c1, float& c2, float& c3,
                                                unsigned a0, unsigned a1, unsigned a2, unsigned a3,
                                                unsigned b0, unsigned b1) {
    asm volatile("mma.sync.aligned.m16n8k16.row.col.f32.bf16.bf16.f32 "
                 "{%0,%1,%2,%3}, {%4,%5,%6,%7}, {%8,%9}, {%0,%1,%2,%3};"
                 : "+f"(c0), "+f"(c1), "+f"(c2), "+f"(c3)
                 : "r"(a0), "r"(a1), "r"(a2), "r"(a3), "r"(b0), "r"(b1));
}

static __device__ __forceinline__ unsigned pack_bf16(float x, float y) {
    __nv_bfloat162 v = __floats2bfloat162_rn(x, y);
    unsigned u;
    memcpy(&u, &v, 4);
    return u;
}

static __device__ __forceinline__ unsigned short f2bf(float x) {
    __nv_bfloat16 v = __float2bfloat16(x);
    unsigned short u;
    memcpy(&u, &v, 2);
    return u;
}

static __device__ __forceinline__ float bf2f(unsigned short u) {
    __nv_bfloat16 v;
    memcpy(&v, &u, 2);
    return __bfloat162float(v);
}

static __device__ __forceinline__ void cp16(unsigned saddr, const void* gaddr) {
    asm volatile("cp.async.cg.shared.global [%0], [%1], 16;\n"
                 :: "r"(saddr), "l"(gaddr));
}
static __device__ __forceinline__ void cp_commit() {
    asm volatile("cp.async.commit_group;\n");
}
template <int N>
static __device__ __forceinline__ void cp_wait() {
    asm volatile("cp.async.wait_group %0;\n" :: "n"(N));
}

// Grid barrier: all NCTA CTAs resident.
static __device__ __forceinline__ void gridbar() {
    __threadfence();
    __syncthreads();
    if (threadIdx.x == 0) {
        unsigned gen = g_bar_gen;
        if (atomicAdd(&g_bar_cnt, 1) == NCTA - 1) {
            g_bar_cnt = 0;
            __threadfence();
            g_bar_gen = gen + 1;
        } else {
            while (g_bar_gen == gen) { }
            __threadfence();
        }
    }
    __syncthreads();
}

// ---------------------------------------------------------------------------
// Packing kernels (hi/lo split, pairing baked into column order)
//   A' columns: [hi(0..K), lo(0..K), hi(0..K)]
//   W' columns: [hi(0..K), hi(0..K), lo(0..K)]   (n-major rows)
//   => Sum over K'=3K gives a_hi*w_hi + a_lo*w_hi + a_hi*w_lo  (~fp32-accurate)
// ---------------------------------------------------------------------------
__global__ void pack_a_kernel(const float* __restrict__ A,
                              unsigned short* __restrict__ Ap)
{
    const size_t idx  = (size_t)blockIdx.x * blockDim.x + threadIdx.x;
    const size_t base = idx * 4;                    // 4 floats per thread
    const size_t m    = base >> 9;                  // /512
    const int    k    = (int)(base & 511);
    const float4 v = *(const float4*)(A + base);

    unsigned short h0 = f2bf(v.x), h1 = f2bf(v.y), h2 = f2bf(v.z), h3 = f2bf(v.w);
    unsigned short l0 = f2bf(v.x - bf2f(h0));
    unsigned short l1 = f2bf(v.y - bf2f(h1));
    unsigned short l2 = f2bf(v.z - bf2f(h2));
    unsigned short l3 = f2bf(v.w - bf2f(h3));

    uint2 hv, lv;
    hv.x = (unsigned)h0 | ((unsigned)h1 << 16);
    hv.y = (unsigned)h2 | ((unsigned)h3 << 16);
    lv.x = (unsigned)l0 | ((unsigned)l1 << 16);
    lv.y = (unsigned)l2 | ((unsigned)l3 << 16);

    unsigned short* row = Ap + m * KP;
    *(uint2*)(row + k)        = hv;
    *(uint2*)(row + 512 + k)  = lv;
    *(uint2*)(row + 1024 + k) = hv;
}

// W [K=512][N] fp32 -> Wp [N][1536] bf16 n-major, [hi, hi, lo]
__global__ void pack_w_kernel(const float* __restrict__ W,
                              unsigned short* __restrict__ Wp, int N)
{
    const int idx = blockIdx.x * blockDim.x + threadIdx.x;
    if (idx >= N * 512) return;
    const int n = idx / 512;
    const int k = idx % 512;
    const float v = W[(size_t)k * N + n];
    unsigned short hi = f2bf(v);
    unsigned short lo = f2bf(v - bf2f(hi));
    unsigned short* row = Wp + (size_t)n * KP;
    row[k]        = hi;
    row[512 + k]  = hi;
    row[1024 + k] = lo;
}

// ---------------------------------------------------------------------------
// bf16 tensor-core GEMM: C[M,N] = act(A'[M,Kp] @ W'[N,Kp]^T + bias)
// BM=128, BN=128, BK=32, 256 threads, 8 warps (2m x 4n), warp tile 64x32.
// PACK: write hi/lo/hi packed bf16 rows of width 1536 (for GEMM1 -> hid).
// else: write fp32 [M][N].
// ---------------------------------------------------------------------------
#define TSTRIDE 40    // halves per smem tile row (32 + 8 pad): ldmatrix conflict-free

template <bool RELU, bool PACK>
__global__ __launch_bounds__(256, 2)
void bgemm_kernel(const unsigned short* __restrict__ Ap,
                  const unsigned short* __restrict__ Wp,
                  const float* __restrict__ bias,
                  float* __restrict__ Cf,              // fp32 out (if !PACK)
                  unsigned short* __restrict__ Cp,     // packed out (if PACK)
                  int N)
{
    __shared__ unsigned short As[2][128 * TSTRIDE];
    __shared__ unsigned short Bs[2][128 * TSTRIDE];

    const int tid  = threadIdx.x;
    const int m0   = blockIdx.y * 128;
    const int n0   = blockIdx.x * 128;
    const int wid  = tid >> 5;
    const int lane = tid & 31;
    const int wm   = wid & 1;        // 0..1
    const int wn   = wid >> 1;       // 0..3

    // loader mapping: row = tid/2 (0..127), col = (tid&1)*16 halves
    const int lrow = tid >> 1;
    const int lcol = (tid & 1) * 16;
    const unsigned short* Ag = Ap + (size_t)(m0 + lrow) * KP + lcol;
    const unsigned short* Bg = Wp + (size_t)(n0 + lrow) * KP + lcol;
    unsigned sa[2], sb[2];
    sa[0] = smem_u32(&As[0][lrow * TSTRIDE + lcol]);
    sa[1] = smem_u32(&As[1][lrow * TSTRIDE + lcol]);
    sb[0] = smem_u32(&Bs[0][lrow * TSTRIDE + lcol]);
    sb[1] = smem_u32(&Bs[1][lrow * TSTRIDE + lcol]);

    const unsigned uA0 = smem_u32(&As[0][0]);
    const unsigned uB0 = smem_u32(&Bs[0][0]);

    // ldmatrix lane mapping (shared by A and B fragments)
    const int aj  = lane >> 3;
    const int ar  = (aj & 1) * 8 + (lane & 7);
    const int akq = (aj >> 1) * 8;

    float acc[4][4][4];
#pragma unroll
    for (int i = 0; i < 4; i++)
#pragma unroll
        for (int j = 0; j < 4; j++)
#pragma unroll
            for (int q = 0; q < 4; q++) acc[i][j][q] = 0.0f;

    // prologue: stage 0
    {
        cp16(sa[0],      Ag);
        cp16(sa[0] + 16, Ag + 8);
        cp16(sb[0],      Bg);
        cp16(sb[0] + 16, Bg + 8);
        cp_commit();
    }

    const int NITER = KP / 32;   // 48
    for (int it = 0; it < NITER; it++) {
        const int s = it & 1;
        if (it + 1 < NITER) {
            const int ns = (it + 1) & 1;
            const int k0 = (it + 1) * 32;
            cp16(sa[ns],      Ag + k0);
            cp16(sa[ns] + 16, Ag + k0 + 8);
            cp16(sb[ns],      Bg + k0);
            cp16(sb[ns] + 16, Bg + k0 + 8);
            cp_commit();
            cp_wait<1>();
        } else {
            cp_wait<0>();
        }
        __syncthreads();

        const unsigned uA = uA0 + (unsigned)s * 128 * TSTRIDE * 2;
        const unsigned uB = uB0 + (unsigned)s * 128 * TSTRIDE * 2;

#pragma unroll
        for (int kk = 0; kk < 32; kk += 16) {
            unsigned a[4][4], b[2][4];
#pragma unroll
            for (int mi = 0; mi < 4; mi++)
                ldsm_x4(a[mi][0], a[mi][1], a[mi][2], a[mi][3],
                        uA + (unsigned)((wm * 64 + mi * 16 + ar) * TSTRIDE + kk + akq) * 2);
#pragma unroll
            for (int p = 0; p < 2; p++)
                ldsm_x4(b[p][0], b[p][1], b[p][2], b[p][3],
                        uB + (unsigned)((wn * 32 + p * 16 + ar) * TSTRIDE + kk + akq) * 2);
#pragma unroll
            for (int mi = 0; mi < 4; mi++) {
#pragma unroll
                for (int p = 0; p < 2; p++) {
                    mma_bf16(acc[mi][2*p][0], acc[mi][2*p][1], acc[mi][2*p][2], acc[mi][2*p][3],
                             a[mi][0], a[mi][1], a[mi][2], a[mi][3], b[p][0], b[p][2]);
                    mma_bf16(acc[mi][2*p+1][0], acc[mi][2*p+1][1], acc[mi][2*p+1][2], acc[mi][2*p+1][3],
                             a[mi][0], a[mi][1], a[mi][2], a[mi][3], b[p][1], b[p][3]);
                }
            }
        }
        __syncthreads();
    }

    // epilogue
    const int quad = lane >> 2;
    const int tq   = lane & 3;
#pragma unroll
    for (int mi = 0; mi < 4; mi++) {
#pragma unroll
        for (int ni = 0; ni < 4; ni++) {
            const int n = n0 + wn * 32 + ni * 8 + tq * 2;
            const float bb0 = bias[n], bb1 = bias[n + 1];
#pragma unroll
            for (int half = 0; half < 2; half++) {
                const int m = m0 + wm * 64 + mi * 16 + quad + half * 8;
                float v0 = acc[mi][ni][half * 2 + 0] + bb0;
                float v1 = acc[mi][ni][half * 2 + 1] + bb1;
                if (RELU) { v0 = fmaxf(v0, 0.f); v1 = fmaxf(v1, 0.f); }
                if (PACK) {
                    unsigned short h0 = f2bf(v0), h1 = f2bf(v1);
                    unsigned short l0 = f2bf(v0 - bf2f(h0));
                    unsigned short l1 = f2bf(v1 - bf2f(h1));
                    unsigned hv = (unsigned)h0 | ((unsigned)h1 << 16);
                    unsigned lv = (unsigned)l0 | ((unsigned)l1 << 16);
                    unsigned short* row = Cp + (size_t)m * KP;
                    *(unsigned*)(row + n)        = hv;
                    *(unsigned*)(row + 512 + n)  = lv;
                    *(unsigned*)(row + 1024 + n) = hv;
                } else {
                    float2 v; v.x = v0; v.y = v1;
                    *(float2*)(Cf + (size_t)m * N + n) = v;
                }
            }
        }
    }
}

// ---------------------------------------------------------------------------
// Persistent tensor-core recurrence kernel (unchanged from round 2).
// ---------------------------------------------------------------------------
#define WS1_STRIDE 1032
#define WS2_STRIDE 520
#define ACH_STRIDE 264
#define H1S_STRIDE 520

#define OFF_WS1  0
#define OFF_WS2  (OFF_WS1 + 32 * WS1_STRIDE * 2)
#define OFF_ACH  (OFF_WS2 + 64 * WS2_STRIDE * 2)
#define OFF_H1S  (OFF_ACH + 32 * ACH_STRIDE * 2)
#define OFF_B1   (OFF_H1S + 32 * H1S_STRIDE * 2)
#define OFF_B2   (OFF_B1 + 32 * 4)
#define OFF_LEN  (OFF_B2 + 64 * 4)
#define SMEM_TOTAL (OFF_LEN + 32 * 4)

__global__ __launch_bounds__(NTHR, 1)
void recurrence_tc(const float* __restrict__ W1h,
                   const float* __restrict__ b1h,
                   const float* __restrict__ W2h,
                   const float* __restrict__ b2h,
                   const int*   __restrict__ lens,
                   float* __restrict__ out)
{
    extern __shared__ char smem[];
    unsigned short* ws1 = (unsigned short*)(smem + OFF_WS1);
    unsigned short* ws2 = (unsigned short*)(smem + OFF_WS2);
    unsigned short* ach = (unsigned short*)(smem + OFF_ACH);
    unsigned short* h1s = (unsigned short*)(smem + OFF_H1S);
    float* b1s = (float*)(smem + OFF_B1);
    float* b2s = (float*)(smem + OFF_B2);
    int*   lns = (int*)(smem + OFF_LEN);

    const unsigned u_ws1 = smem_u32(ws1);
    const unsigned u_ws2 = smem_u32(ws2);
    const unsigned u_ach = smem_u32(ach);
    const unsigned u_h1s = smem_u32(h1s);

    const int tid  = threadIdx.x;
    const int cta  = blockIdx.x;
    const int wid  = tid >> 5;
    const int lane = tid & 31;
    const int quad = lane >> 2;
    const int tq   = lane & 3;

    const int rA = (cta >> 4) * 32;
    const int cA = (cta & 15) * 32;
    const int rB = (cta >> 4) * 32;
    const int cB = (cta & 15) * 64;

    const int mh = wid & 1;
    const int nb = wid >> 1;
    const int np = wid >> 1;

    for (int i = tid; i < 1024 * 32; i += NTHR) {
        int k = i >> 5, n = i & 31;
        ws1[n * WS1_STRIDE + k] = f2bf(W1h[(size_t)k * HALF_H + cA + n]);
    }
    for (int i = tid; i < 512 * 64; i += NTHR) {
        int k = i >> 6, n = i & 63;
        ws2[n * WS2_STRIDE + k] = f2bf(W2h[(size_t)k * HIDDEN + cB + n]);
    }
    if (tid < 32) { b1s[tid] = b1h[cA + tid]; lns[tid] = lens[rB + tid]; }
    if (tid < 64) b2s[tid] = b2h[cB + tid];

    {
        unsigned* hz = (unsigned*)g_h_bf16;
        for (int i = tid; i < 1024; i += NTHR) hz[cta * 1024 + i] = 0u;
    }

    float hreg[2][4];
#pragma unroll
    for (int b = 0; b < 2; b++)
#pragma unroll
        for (int j = 0; j < 4; j++) hreg[b][j] = 0.0f;

    __syncthreads();
    gridbar();

    const int aj   = lane >> 3;
    const int arow = mh * 16 + (aj & 1) * 8 + (lane & 7);
    const int akq  = (aj >> 1) * 8;
    const int li   = lane & 15;
    const int brow_in = li & 7;
    const int bkq  = (li >> 3) * 8;

    for (int t = 0; t < SEQLEN; t++) {
        // ================= PHASE A =================
        float ca[4] = {0.f, 0.f, 0.f, 0.f};
        for (int ch = 0; ch < 4; ch++) {
            const int kbase = ch * 256;
            __syncthreads();
#pragma unroll
            for (int j = 0; j < 4; j++) {
                int lin  = tid + j * NTHR;
                int row  = lin >> 5;
                int colv = (lin & 31) * 8;
                uint4 v = __ldcg((const uint4*)(g_h_bf16 + (size_t)(rA + row) * HIDDEN + kbase + colv));
                *(uint4*)(ach + row * ACH_STRIDE + colv) = v;
            }
            __syncthreads();
#pragma unroll 4
            for (int kk = 0; kk < 256; kk += 16) {
                unsigned a0, a1, a2, a3, b0, b1;
                ldsm_x4(a0, a1, a2, a3, u_ach + (unsigned)(arow * ACH_STRIDE + kk + akq) * 2);
                ldsm_x2(b0, b1, u_ws1 + (unsigned)((nb * 8 + brow_in) * WS1_STRIDE + kbase + kk + bkq) * 2);
                mma_bf16(ca[0], ca[1], ca[2], ca[3], a0, a1, a2, a3, b0, b1);
            }
        }
        {
            const int n = nb * 8 + tq * 2;
            const int m0w = mh * 16 + quad;
            float v0 = fmaxf(ca[0] + b1s[n], 0.f);
            float v1 = fmaxf(ca[1] + b1s[n + 1], 0.f);
            float v2 = fmaxf(ca[2] + b1s[n], 0.f);
            float v3 = fmaxf(ca[3] + b1s[n + 1], 0.f);
            __stcg((unsigned*)(g_h1_bf16 + (size_t)(rA + m0w) * HALF_H + cA + n), pack_bf16(v0, v1));
            __stcg((unsigned*)(g_h1_bf16 + (size_t)(rA + m0w + 8) * HALF_H + cA + n), pack_bf16(v2, v3));
        }
        gridbar();

        // ================= PHASE B =================
        __syncthreads();
#pragma unroll
        for (int j = 0; j < 8; j++) {
            int lin  = tid + j * NTHR;
            int row  = lin >> 6;
            int colv = (lin & 63) * 8;
            uint4 v = __ldcg((const uint4*)(g_h1_bf16 + (size_t)(rB + row) * HALF_H + colv));
            *(uint4*)(h1s + row * H1S_STRIDE + colv) = v;
        }
        __syncthreads();

        float cb[2][4];
#pragma unroll
        for (int b = 0; b < 2; b++)
#pragma unroll
            for (int j = 0; j < 4; j++) cb[b][j] = 0.f;

#pragma unroll 4
        for (int kk = 0; kk < 512; kk += 16) {
            unsigned a0, a1, a2, a3;
            ldsm_x4(a0, a1, a2, a3, u_h1s + (unsigned)(arow * H1S_STRIDE + kk + akq) * 2);
#pragma unroll
            for (int b = 0; b < 2; b++) {
                unsigned b0, b1;
                ldsm_x2(b0, b1, u_ws2 + (unsigned)((np * 16 + b * 8 + brow_in) * WS2_STRIDE + kk + bkq) * 2);
                mma_bf16(cb[b][0], cb[b][1], cb[b][2], cb[b][3], a0, a1, a2, a3, b0, b1);
            }
        }

#pragma unroll
        for (int b = 0; b < 2; b++) {
            const int n = np * 16 + b * 8 + tq * 2;
            const float bb0 = b2s[n], bb1 = b2s[n + 1];
#pragma unroll
            for (int half = 0; half < 2; half++) {
                const int m = mh * 16 + quad + half * 8;
                const int bat = rB + m;
                const int col = cB + n;
                const size_t oidx = ((size_t)bat * SEQLEN + t) * HIDDEN + col;
                float xh0 = out[oidx], xh1 = out[oidx + 1];
                float nv0 = tanhf(xh0 + cb[b][half * 2 + 0] + bb0);
                float nv1 = tanhf(xh1 + cb[b][half * 2 + 1] + bb1);
                bool ok = t < lns[m];
                float h0 = ok ? nv0 : hreg[b][half * 2 + 0];
                float h1 = ok ? nv1 : hreg[b][half * 2 + 1];
                hreg[b][half * 2 + 0] = h0;
                hreg[b][half * 2 + 1] = h1;
                out[oidx]     = h0;
                out[oidx + 1] = h1;
                __stcg((unsigned*)(g_h_bf16 + (size_t)bat * HIDDEN + col), pack_bf16(h0, h1));
            }
        }
        gridbar();
    }
}

// ---------------------------------------------------------------------------
extern "C" void kernel_launch(void* const* d_in, const int* in_sizes, int n_in,
                              void* d_out, int out_size)
{
    const float* seq  = (const float*)d_in[0];
    const int*   lens = (const int*)  d_in[1];
    const float* w1x  = (const float*)d_in[2];
    const float* b1x  = (const float*)d_in[3];
    const float* w2x  = (const float*)d_in[4];
    const float* b2x  = (const float*)d_in[5];
    const float* w1h  = (const float*)d_in[6];
    const float* b1h  = (const float*)d_in[7];
    const float* w2h  = (const float*)d_in[8];
    const float* b2h  = (const float*)d_in[9];
    float* out = (float*)d_out;

    unsigned short *a1p, *hidp, *w1xp, *w2xp;
    cudaGetSymbolAddress((void**)&a1p,  g_a1p);
    cudaGetSymbolAddress((void**)&hidp, g_hidp);
    cudaGetSymbolAddress((void**)&w1xp, g_w1xp);
    cudaGetSymbolAddress((void**)&w2xp, g_w2xp);

    static bool attr_set = false;
    if (!attr_set) {
        cudaFuncSetAttribute(recurrence_tc,
                             cudaFuncAttributeMaxDynamicSharedMemorySize, SMEM_TOTAL);
        attr_set = true;
    }

    // Pack operands (hi/lo split)
    pack_a_kernel<<<(NTOK * EMB / 4) / 256, 256>>>(seq, a1p);
    pack_w_kernel<<<(HALF_H * 512 + 255) / 256, 256>>>(w1x, w1xp, HALF_H);
    pack_w_kernel<<<(HIDDEN * 512 + 255) / 256, 256>>>(w2x, w2xp, HIDDEN);

    // K1: hidp = pack(relu(seq @ w1x + b1x))   (bf16 TC, split-K'=1536)
    bgemm_kernel<true, true><<<dim3(HALF_H / 128, NTOK / 128), 256>>>(
        a1p, w1xp, b1x, nullptr, hidp, HALF_H);

    // K2: out = hid @ w2x + b2x   (xh, fp32 out)
    bgemm_kernel<false, false><<<dim3(HIDDEN / 128, NTOK / 128), 256>>>(
        hidp, w2xp, b2x, out, nullptr, HIDDEN);

    // K3: persistent tensor-core recurrence
    recurrence_tc<<<NCTA, NTHR, SMEM_TOTAL>>>(w1h, b1h, w2h, b2h, lens, out);
}

// round 4
// speedup vs baseline: 3.2896x; 1.0805x over previous
#include <cuda_runtime.h>
#include <cuda_bf16.h>
#include <math.h>
#include <string.h>

// Problem constants (fixed by the dataset)
#define EMB     512
#define HIDDEN  1024
#define HALF_H  512
#define BATCH   256
#define SEQLEN  512
#define NTOK    (BATCH * SEQLEN)   // 131072
#define KP      1536               // 3 * 512 packed-K for split-bf16 GEMMs

#define NCTA    128
#define NTHR    256

// ---------------------------------------------------------------------------
// Device globals (allocation-free scratch)
// ---------------------------------------------------------------------------
__device__ unsigned short g_a1p[(size_t)NTOK * KP];    // packed seq   [M][1536]
__device__ unsigned short g_hidp[(size_t)NTOK * KP];   // packed hid1  [M][1536]
__device__ unsigned short g_w1xp[HALF_H * KP];         // packed w1x   [512][1536] (n-major)
__device__ unsigned short g_w2xp[HIDDEN * KP];         // packed w2x   [1024][1536] (n-major)
__device__ unsigned short g_h_bf16[BATCH * HIDDEN];    // h (bf16)
__device__ unsigned short g_h1_bf16[BATCH * HALF_H];   // relu(h@W1h+b1h) (bf16)
__device__ volatile unsigned g_ggen[8 * 32];           // per-group barrier gen (128B apart)
__device__ unsigned g_gcnt[8 * 32];                    // per-group barrier count

// ---------------------------------------------------------------------------
// Helpers
// ---------------------------------------------------------------------------
static __device__ __forceinline__ unsigned smem_u32(const void* p) {
    unsigned a;
    asm("{ .reg .u64 t; cvta.to.shared.u64 t, %1; cvt.u32.u64 %0, t; }"
        : "=r"(a) : "l"(p));
    return a;
}

static __device__ __forceinline__ void ldsm_x4(unsigned& r0, unsigned& r1,
                                               unsigned& r2, unsigned& r3,
                                               unsigned addr) {
    asm volatile("ldmatrix.sync.aligned.m8n8.x4.shared.b16 {%0,%1,%2,%3}, [%4];"
                 : "=r"(r0), "=r"(r1), "=r"(r2), "=r"(r3) : "r"(addr));
}

static __device__ __forceinline__ void ldsm_x2(unsigned& r0, unsigned& r1,
                                               unsigned addr) {
    asm volatile("ldmatrix.sync.aligned.m8n8.x2.shared.b16 {%0,%1}, [%2];"
                 : "=r"(r0), "=r"(r1) : "r"(addr));
}

static __device__ __forceinline__ void mma_bf16(float& c0, float& c1, float& c2, float& c3,
                                                unsigned a0, unsigned a1, unsigned a2, unsigned a3,
                                                unsigned b0, unsigned b1) {
    asm volatile("mma.sync.aligned.m16n8k16.row.col.f32.bf16.bf16.f32 "
                 "{%0,%1,%2,%3}, {%4,%5,%6,%7}, {%8,%9}, {%0,%1,%2,%3};"
                 : "+f"(c0), "+f"(c1), "+f"(c2), "+f"(c3)
                 : "r"(a0), "r"(a1), "r"(a2), "r"(a3), "r"(b0), "r"(b1));
}

static __device__ __forceinline__ unsigned pack_bf16(float x, float y) {
    __nv_bfloat162 v = __floats2bfloat162_rn(x, y);
    unsigned u;
    memcpy(&u, &v, 4);
    return u;
}

static __device__ __forceinline__ unsigned short f2bf(float x) {
    __nv_bfloat16 v = __float2bfloat16(x);
    unsigned short u;
    memcpy(&u, &v, 2);
    return u;
}

static __device__ __forceinline__ float bf2f(unsigned short u) {
    __nv_bfloat16 v;
    memcpy(&v, &u, 2);
    return __bfloat162float(v);
}

static __device__ __forceinline__ void cp16(unsigned saddr, const void* gaddr) {
    asm volatile("cp.async.cg.shared.global [%0], [%1], 16;\n"
                 :: "r"(saddr), "l"(gaddr));
}
static __device__ __forceinline__ void cp_commit() {
    asm volatile("cp.async.commit_group;\n");
}
template <int N>
static __device__ __forceinline__ void cp_wait() {
    asm volatile("cp.async.wait_group %0;\n" :: "n"(N));
}

// Per-row-group barrier: 16 CTAs per group, separate cache lines per group.
static __device__ __forceinline__ void groupbar(int g) {
    __threadfence();
    __syncthreads();
    if (threadIdx.x == 0) {
        const int gi = g * 32;
        unsigned gen = g_ggen[gi];
        if (atomicAdd(&g_gcnt[gi], 1) == 15) {
            g_gcnt[gi] = 0;
            __threadfence();
            g_ggen[gi] = gen + 1;
        } else {
            while (g_ggen[gi] == gen) { }
            __threadfence();
        }
    }
    __syncthreads();
}

// ---------------------------------------------------------------------------
// Packing kernels (hi/lo split, pairing baked into column order)
// ---------------------------------------------------------------------------
__global__ void pack_a_kernel(const float* __restrict__ A,
                              unsigned short* __restrict__ Ap)
{
    const size_t idx  = (size_t)blockIdx.x * blockDim.x + threadIdx.x;
    const size_t base = idx * 4;
    const size_t m    = base >> 9;
    const int    k    = (int)(base & 511);
    const float4 v = *(const float4*)(A + base);

    unsigned short h0 = f2bf(v.x), h1 = f2bf(v.y), h2 = f2bf(v.z), h3 = f2bf(v.w);
    unsigned short l0 = f2bf(v.x - bf2f(h0));
    unsigned short l1 = f2bf(v.y - bf2f(h1));
    unsigned short l2 = f2bf(v.z - bf2f(h2));
    unsigned short l3 = f2bf(v.w - bf2f(h3));

    uint2 hv, lv;
    hv.x = (unsigned)h0 | ((unsigned)h1 << 16);
    hv.y = (unsigned)h2 | ((unsigned)h3 << 16);
    lv.x = (unsigned)l0 | ((unsigned)l1 << 16);
    lv.y = (unsigned)l2 | ((unsigned)l3 << 16);

    unsigned short* row = Ap + m * KP;
    *(uint2*)(row + k)        = hv;
    *(uint2*)(row + 512 + k)  = lv;
    *(uint2*)(row + 1024 + k) = hv;
}

__global__ void pack_w_kernel(const float* __restrict__ W,
                              unsigned short* __restrict__ Wp, int N)
{
    const int idx = blockIdx.x * blockDim.x + threadIdx.x;
    if (idx >= N * 512) return;
    const int n = idx / 512;
    const int k = idx % 512;
    const float v = W[(size_t)k * N + n];
    unsigned short hi = f2bf(v);
    unsigned short lo = f2bf(v - bf2f(hi));
    unsigned short* row = Wp + (size_t)n * KP;
    row[k]        = hi;
    row[512 + k]  = hi;
    row[1024 + k] = lo;
}

// ---------------------------------------------------------------------------
// bf16 tensor-core GEMM, 4-stage cp.async pipeline, 1 sync/iter.
// BM=128, BN=128, BK=32, 256 threads, 8 warps (2m x 4n), warp tile 64x32.
// ---------------------------------------------------------------------------
#define TSTRIDE 40                             // halves per smem tile row
#define GSTAGES 4
#define GST_HALVES (128 * TSTRIDE)             // 5120
#define GST_BYTES  (GST_HALVES * 2)            // 10240
#define GSMEM_TOTAL (GSTAGES * GST_BYTES * 2)  // 81920

template <bool RELU, bool PACK>
__global__ __launch_bounds__(256, 2)
void bgemm_kernel(const unsigned short* __restrict__ Ap,
                  const unsigned short* __restrict__ Wp,
                  const float* __restrict__ bias,
                  float* __restrict__ Cf,
                  unsigned short* __restrict__ Cp,
                  int N)
{
    extern __shared__ char gsm[];
    unsigned short* As = (unsigned short*)gsm;
    unsigned short* Bs = (unsigned short*)(gsm + GSTAGES * GST_BYTES);

    const int tid  = threadIdx.x;
    const int m0   = blockIdx.y * 128;
    const int n0   = blockIdx.x * 128;
    const int wid  = tid >> 5;
    const int lane = tid & 31;
    const int wm   = wid & 1;
    const int wn   = wid >> 1;

    const int lrow = tid >> 1;
    const int lcol = (tid & 1) * 16;
    const unsigned short* Ag = Ap + (size_t)(m0 + lrow) * KP + lcol;
    const unsigned short* Bg = Wp + (size_t)(n0 + lrow) * KP + lcol;

    const unsigned uA0 = smem_u32(As);
    const unsigned uB0 = smem_u32(Bs);
    const unsigned sa0 = uA0 + (unsigned)(lrow * TSTRIDE + lcol) * 2;
    const unsigned sb0 = uB0 + (unsigned)(lrow * TSTRIDE + lcol) * 2;

    const int aj  = lane >> 3;
    const int ar  = (aj & 1) * 8 + (lane & 7);
    const int akq = (aj >> 1) * 8;

    float acc[4][4][4];
#pragma unroll
    for (int i = 0; i < 4; i++)
#pragma unroll
        for (int j = 0; j < 4; j++)
#pragma unroll
            for (int q = 0; q < 4; q++) acc[i][j][q] = 0.0f;

#define G_ISSUE(it_) do {                                              \
        const int _buf = (it_) & (GSTAGES - 1);                        \
        const int _k0  = (it_) * 32;                                   \
        cp16(sa0 + _buf * GST_BYTES,      Ag + _k0);                   \
        cp16(sa0 + _buf * GST_BYTES + 16, Ag + _k0 + 8);               \
        cp16(sb0 + _buf * GST_BYTES,      Bg + _k0);                   \
        cp16(sb0 + _buf * GST_BYTES + 16, Bg + _k0 + 8);               \
        cp_commit();                                                   \
    } while (0)

    G_ISSUE(0); G_ISSUE(1); G_ISSUE(2);

    const int NITER = KP / 32;   // 48
    for (int it = 0; it < NITER; it++) {
        if (it < NITER - 2)       cp_wait<2>();
        else if (it == NITER - 2) cp_wait<1>();
        else                      cp_wait<0>();
        __syncthreads();
        if (it + 3 < NITER) G_ISSUE(it + 3);

        const int buf = it & (GSTAGES - 1);
        const unsigned uA = uA0 + (unsigned)buf * GST_BYTES;
        const unsigned uB = uB0 + (unsigned)buf * GST_BYTES;

#pragma unroll
        for (int kk = 0; kk < 32; kk += 16) {
            unsigned a[4][4], b[2][4];
#pragma unroll
            for (int mi = 0; mi < 4; mi++)
                ldsm_x4(a[mi][0], a[mi][1], a[mi][2], a[mi][3],
                        uA + (unsigned)((wm * 64 + mi * 16 + ar) * TSTRIDE + kk + akq) * 2);
#pragma unroll
            for (int p = 0; p < 2; p++)
                ldsm_x4(b[p][0], b[p][1], b[p][2], b[p][3],
                        uB + (unsigned)((wn * 32 + p * 16 + ar) * TSTRIDE + kk + akq) * 2);
#pragma unroll
            for (int mi = 0; mi < 4; mi++) {
#pragma unroll
                for (int p = 0; p < 2; p++) {
                    mma_bf16(acc[mi][2*p][0], acc[mi][2*p][1], acc[mi][2*p][2], acc[mi][2*p][3],
                             a[mi][0], a[mi][1], a[mi][2], a[mi][3], b[p][0], b[p][2]);
                    mma_bf16(acc[mi][2*p+1][0], acc[mi][2*p+1][1], acc[mi][2*p+1][2], acc[mi][2*p+1][3],
                             a[mi][0], a[mi][1], a[mi][2], a[mi][3], b[p][1], b[p][3]);
                }
            }
        }
    }
#undef G_ISSUE

    // epilogue
    const int quad = lane >> 2;
    const int tq   = lane & 3;
#pragma unroll
    for (int mi = 0; mi < 4; mi++) {
#pragma unroll
        for (int ni = 0; ni < 4; ni++) {
            const int n = n0 + wn * 32 + ni * 8 + tq * 2;
            const float bb0 = bias[n], bb1 = bias[n + 1];
#pragma unroll
            for (int half = 0; half < 2; half++) {
                const int m = m0 + wm * 64 + mi * 16 + quad + half * 8;
                float v0 = acc[mi][ni][half * 2 + 0] + bb0;
                float v1 = acc[mi][ni][half * 2 + 1] + bb1;
                if (RELU) { v0 = fmaxf(v0, 0.f); v1 = fmaxf(v1, 0.f); }
                if (PACK) {
                    unsigned short h0 = f2bf(v0), h1 = f2bf(v1);
                    unsigned short l0 = f2bf(v0 - bf2f(h0));
                    unsigned short l1 = f2bf(v1 - bf2f(h1));
                    unsigned hv = (unsigned)h0 | ((unsigned)h1 << 16);
                    unsigned lv = (unsigned)l0 | ((unsigned)l1 << 16);
                    unsigned short* row = Cp + (size_t)m * KP;
                    *(unsigned*)(row + n)        = hv;
                    *(unsigned*)(row + 512 + n)  = lv;
                    *(unsigned*)(row + 1024 + n) = hv;
                } else {
                    float2 v; v.x = v0; v.y = v1;
                    *(float2*)(Cf + (size_t)m * N + n) = v;
                }
            }
        }
    }
}

// ---------------------------------------------------------------------------
// Persistent tensor-core recurrence kernel.
// 8 independent row groups of 16 CTAs; group-local barriers only.
// Phase A h-staging via 3-buffer cp.async ring; phase B staging via cp.async.
// ---------------------------------------------------------------------------
#define WS1_STRIDE 1032
#define WS2_STRIDE 520
#define ACH_STRIDE 264
#define H1S_STRIDE 520
#define ACH_BUF    (32 * ACH_STRIDE)              // halves per ach buffer

#define OFF_WS1  0
#define OFF_WS2  (OFF_WS1 + 32 * WS1_STRIDE * 2)          // 66048
#define OFF_ACH  (OFF_WS2 + 64 * WS2_STRIDE * 2)          // 132608
#define OFF_H1S  (OFF_ACH + 3 * ACH_BUF * 2)              // 183296
#define OFF_B1   (OFF_H1S + 32 * H1S_STRIDE * 2)          // 216576
#define OFF_B2   (OFF_B1 + 32 * 4)                        // 216704
#define OFF_LEN  (OFF_B2 + 64 * 4)                        // 216960
#define SMEM_TOTAL (OFF_LEN + 32 * 4)                     // 217088

__global__ __launch_bounds__(NTHR, 1)
void recurrence_tc(const float* __restrict__ W1h,
                   const float* __restrict__ b1h,
                   const float* __restrict__ W2h,
                   const float* __restrict__ b2h,
                   const int*   __restrict__ lens,
                   float* __restrict__ out)
{
    extern __shared__ char smem[];
    unsigned short* ws1 = (unsigned short*)(smem + OFF_WS1);
    unsigned short* ws2 = (unsigned short*)(smem + OFF_WS2);
    unsigned short* h1s = (unsigned short*)(smem + OFF_H1S);
    float* b1s = (float*)(smem + OFF_B1);
    float* b2s = (float*)(smem + OFF_B2);
    int*   lns = (int*)(smem + OFF_LEN);

    const unsigned u_ws1 = smem_u32(ws1);
    const unsigned u_ws2 = smem_u32(ws2);
    const unsigned u_ach = smem_u32(smem + OFF_ACH);
    const unsigned u_h1s = smem_u32(h1s);

    const int tid  = threadIdx.x;
    const int cta  = blockIdx.x;
    const int wid  = tid >> 5;
    const int lane = tid & 31;
    const int quad = lane >> 2;
    const int tq   = lane & 3;

    const int grp = cta >> 4;                // 0..7 row group
    const int mem = cta & 15;                // member within group
    const int rA = grp * 32;                 // batch rows (both phases)
    const int cA = mem * 32;                 // h1 cols (phase A)
    const int cB = mem * 64;                 // h cols (phase B)

    const int mh = wid & 1;
    const int nb = wid >> 1;
    const int np = wid >> 1;

    for (int i = tid; i < 1024 * 32; i += NTHR) {
        int k = i >> 5, n = i & 31;
        ws1[n * WS1_STRIDE + k] = f2bf(W1h[(size_t)k * HALF_H + cA + n]);
    }
    for (int i = tid; i < 512 * 64; i += NTHR) {
        int k = i >> 6, n = i & 63;
        ws2[n * WS2_STRIDE + k] = f2bf(W2h[(size_t)k * HIDDEN + cB + n]);
    }
    if (tid < 32) { b1s[tid] = b1h[cA + tid]; lns[tid] = lens[rA + tid]; }
    if (tid < 64) b2s[tid] = b2h[cB + tid];

    // zero this group's h slab (32 rows x 1024 halves = 16384 words over 16 CTAs)
    {
        unsigned* hz = (unsigned*)(g_h_bf16 + (size_t)rA * HIDDEN);
        for (int i = tid; i < 1024; i += NTHR) hz[mem * 1024 + i] = 0u;
    }

    float hreg[2][4];
#pragma unroll
    for (int b = 0; b < 2; b++)
#pragma unroll
        for (int j = 0; j < 4; j++) hreg[b][j] = 0.0f;

    groupbar(grp);

    const int aj   = lane >> 3;
    const int arow = mh * 16 + (aj & 1) * 8 + (lane & 7);
    const int akq  = (aj >> 1) * 8;
    const int li   = lane & 15;
    const int brow_in = li & 7;
    const int bkq  = (li >> 3) * 8;

#define ISSUE_A(ch_) do {                                                   \
        const int _buf = (ch_) % 3;                                         \
        const unsigned _dst = u_ach + (unsigned)_buf * (ACH_BUF * 2);       \
        const int _kb = (ch_) * 256;                                        \
        _Pragma("unroll")                                                   \
        for (int _j = 0; _j < 4; _j++) {                                    \
            int _lin = tid + _j * NTHR;                                     \
            int _row = _lin >> 5;                                           \
            int _cv  = (_lin & 31) * 8;                                     \
            cp16(_dst + (unsigned)(_row * ACH_STRIDE + _cv) * 2,            \
                 g_h_bf16 + (size_t)(rA + _row) * HIDDEN + _kb + _cv);      \
        }                                                                   \
        cp_commit();                                                        \
    } while (0)

    for (int t = 0; t < SEQLEN; t++) {
        // ================= PHASE A =================
        ISSUE_A(0); ISSUE_A(1);
        float ca[4] = {0.f, 0.f, 0.f, 0.f};
        for (int ch = 0; ch < 4; ch++) {
            if (ch < 3) cp_wait<1>(); else cp_wait<0>();
            __syncthreads();
            if (ch + 2 < 4) ISSUE_A(ch + 2);

            const unsigned uach = u_ach + (unsigned)(ch % 3) * (ACH_BUF * 2);
            const int kbase = ch * 256;
#pragma unroll 4
            for (int kk = 0; kk < 256; kk += 16) {
                unsigned a0, a1, a2, a3, b0, b1;
                ldsm_x4(a0, a1, a2, a3, uach + (unsigned)(arow * ACH_STRIDE + kk + akq) * 2);
                ldsm_x2(b0, b1, u_ws1 + (unsigned)((nb * 8 + brow_in) * WS1_STRIDE + kbase + kk + bkq) * 2);
                mma_bf16(ca[0], ca[1], ca[2], ca[3], a0, a1, a2, a3, b0, b1);
            }
        }
        {
            const int n = nb * 8 + tq * 2;
            const int m0w = mh * 16 + quad;
            float v0 = fmaxf(ca[0] + b1s[n], 0.f);
            float v1 = fmaxf(ca[1] + b1s[n + 1], 0.f);
            float v2 = fmaxf(ca[2] + b1s[n], 0.f);
            float v3 = fmaxf(ca[3] + b1s[n + 1], 0.f);
            __stcg((unsigned*)(g_h1_bf16 + (size_t)(rA + m0w) * HALF_H + cA + n), pack_bf16(v0, v1));
            __stcg((unsigned*)(g_h1_bf16 + (size_t)(rA + m0w + 8) * HALF_H + cA + n), pack_bf16(v2, v3));
        }
        groupbar(grp);

        // ================= PHASE B =================
#pragma unroll
        for (int j = 0; j < 8; j++) {
            int lin  = tid + j * NTHR;
            int row  = lin >> 6;
            int colv = (lin & 63) * 8;
            cp16(u_h1s + (unsigned)(row * H1S_STRIDE + colv) * 2,
                 g_h1_bf16 + (size_t)(rA + row) * HALF_H + colv);
        }
        cp_commit();
        cp_wait<0>();
        __syncthreads();

        float cb[2][4];
#pragma unroll
        for (int b = 0; b < 2; b++)
#pragma unroll
            for (int j = 0; j < 4; j++) cb[b][j] = 0.f;

#pragma unroll 4
        for (int kk = 0; kk < 512; kk += 16) {
            unsigned a0, a1, a2, a3;
            ldsm_x4(a0, a1, a2, a3, u_h1s + (unsigned)(arow * H1S_STRIDE + kk + akq) * 2);
#pragma unroll
            for (int b = 0; b < 2; b++) {
                unsigned b0, b1;
                ldsm_x2(b0, b1, u_ws2 + (unsigned)((np * 16 + b * 8 + brow_in) * WS2_STRIDE + kk + bkq) * 2);
                mma_bf16(cb[b][0], cb[b][1], cb[b][2], cb[b][3], a0, a1, a2, a3, b0, b1);
            }
        }

#pragma unroll
        for (int b = 0; b < 2; b++) {
            const int n = np * 16 + b * 8 + tq * 2;
            const float bb0 = b2s[n], bb1 = b2s[n + 1];
#pragma unroll
            for (int half = 0; half < 2; half++) {
                const int m = mh * 16 + quad + half * 8;
                const int bat = rA + m;
                const int col = cB + n;
                const size_t oidx = ((size_t)bat * SEQLEN + t) * HIDDEN + col;
                float xh0 = out[oidx], xh1 = out[oidx + 1];
                float nv0 = tanhf(xh0 + cb[b][half * 2 + 0] + bb0);
                float nv1 = tanhf(xh1 + cb[b][half * 2 + 1] + bb1);
                bool ok = t < lns[m];
                float h0 = ok ? nv0 : hreg[b][half * 2 + 0];
                float h1 = ok ? nv1 : hreg[b][half * 2 + 1];
                hreg[b][half * 2 + 0] = h0;
                hreg[b][half * 2 + 1] = h1;
                out[oidx]     = h0;
                out[oidx + 1] = h1;
                __stcg((unsigned*)(g_h_bf16 + (size_t)bat * HIDDEN + col), pack_bf16(h0, h1));
            }
        }
        groupbar(grp);
    }
#undef ISSUE_A
}

// ---------------------------------------------------------------------------
extern "C" void kernel_launch(void* const* d_in, const int* in_sizes, int n_in,
                              void* d_out, int out_size)
{
    const float* seq  = (const float*)d_in[0];
    const int*   lens = (const int*)  d_in[1];
    const float* w1x  = (const float*)d_in[2];
    const float* b1x  = (const float*)d_in[3];
    const float* w2x  = (const float*)d_in[4];
    const float* b2x  = (const float*)d_in[5];
    const float* w1h  = (const float*)d_in[6];
    const float* b1h  = (const float*)d_in[7];
    const float* w2h  = (const float*)d_in[8];
    const float* b2h  = (const float*)d_in[9];
    float* out = (float*)d_out;

    unsigned short *a1p, *hidp, *w1xp, *w2xp;
    cudaGetSymbolAddress((void**)&a1p,  g_a1p);
    cudaGetSymbolAddress((void**)&hidp, g_hidp);
    cudaGetSymbolAddress((void**)&w1xp, g_w1xp);
    cudaGetSymbolAddress((void**)&w2xp, g_w2xp);

    static bool attr_set = false;
    if (!attr_set) {
        cudaFuncSetAttribute(recurrence_tc,
                             cudaFuncAttributeMaxDynamicSharedMemorySize, SMEM_TOTAL);
        cudaFuncSetAttribute(bgemm_kernel<true, true>,
                             cudaFuncAttributeMaxDynamicSharedMemorySize, GSMEM_TOTAL);
        cudaFuncSetAttribute(bgemm_kernel<false, false>,
                             cudaFuncAttributeMaxDynamicSharedMemorySize, GSMEM_TOTAL);
        attr_set = true;
    }

    // Pack operands (hi/lo split)
    pack_a_kernel<<<(NTOK * EMB / 4) / 256, 256>>>(seq, a1p);
    pack_w_kernel<<<(HALF_H * 512 + 255) / 256, 256>>>(w1x, w1xp, HALF_H);
    pack_w_kernel<<<(HIDDEN * 512 + 255) / 256, 256>>>(w2x, w2xp, HIDDEN);

    // K1: hidp = pack(relu(seq @ w1x + b1x))
    bgemm_kernel<true, true><<<dim3(HALF_H / 128, NTOK / 128), 256, GSMEM_TOTAL>>>(
        a1p, w1xp, b1x, nullptr, hidp, HALF_H);

    // K2: out = hid @ w2x + b2x   (xh)
    bgemm_kernel<false, false><<<dim3(HIDDEN / 128, NTOK / 128), 256, GSMEM_TOTAL>>>(
        hidp, w2xp, b2x, out, nullptr, HIDDEN);

    // K3: persistent tensor-core recurrence (group-local barriers)
    recurrence_tc<<<NCTA, NTHR, SMEM_TOTAL>>>(w1h, b1h, w2h, b2h, lens, out);
}